// round 5
// baseline (speedup 1.0000x reference)
#include <cuda_runtime.h>
#include <cuda_bf16.h>

// Dual marching cubes, GRID=192, ISO=0.
// One thread = TWO cells paired along a: (2*ap, b, c) and (2*ap+1, b, c).
// Shared face corners loaded once; shared-plane y/z edge crossings computed once.
// All stores remain lane-contiguous in c (perfect coalescing).
// Output (float32, concatenated, reference order):
//   verts  [193^3 * 3]       at V_OFF  = 0
//   vmask  [193^3]           at VM_OFF = 21,567,171
//   quads  [3*193*192*192*4] at Q_OFF  = 28,756,228   (16B-aligned)
//   qmask  [3*193*192*192]   at QM_OFF = 114,133,252  (16B-aligned)

#define GD   192
#define C    193
#define C2   (C*C)          // 37249
#define NC   (C*C*C)        // 7,189,057
#define NEX  (C*GD*GD)      // 7,114,752
#define NQ   (3*NEX)
#define V_OFF  0
#define VM_OFF (3*NC)
#define Q_OFF  (VM_OFF + NC)
#define QM_OFF (Q_OFF + 4*NQ)

#define BX 146              // 146*256 = 37376 >= C2

__global__ void __launch_bounds__(256)
dmc_pair(const float* __restrict__ g, float* __restrict__ out)
{
    __shared__ float s[1536];
    const int tid = threadIdx.x;
    const int r   = blockIdx.x * 256 + tid;
    const int ap  = blockIdx.y;
    const bool act = r < C2;
    const int rr  = act ? r : C2 - 1;
    const int c   = rr % C;
    const int b   = rr / C;
    const int gb = b - 1, gc = c - 1;
    const float nrm = 1.0f / (float)(GD - 1);
    float4* qb = (float4*)(out + Q_OFF);

    if (ap < 96) {
        // ---------------- two cells: a = 2*ap and a+1 ----------------
        const int a  = 2 * ap;
        const int ga = a - 1;

        // w[i], i = da*4 + db*2 + dc ; grid pos (ga+da, gb+db, gc+dc), da in 0..2
        float w[12];
        const bool interior = (a >= 2) & (a <= 190) & (b >= 1) & (b <= GD - 1) & (c >= 1) & (c <= GD - 1);
        if (interior) {
            const float* p = g + ((ga * GD + gb) * GD + gc);
            #pragma unroll
            for (int i = 0; i < 12; i++) {
                int da = i >> 2, db = (i >> 1) & 1, dc = i & 1;
                w[i] = __ldg(p + (da * GD + db) * GD + dc);
            }
        } else {
            #pragma unroll
            for (int i = 0; i < 12; i++) {
                int da = i >> 2, db = (i >> 1) & 1, dc = i & 1;
                int x = ga + da, y = gb + db, z = gc + dc;
                bool in = ((unsigned)x < (unsigned)GD) & ((unsigned)y < (unsigned)GD) & ((unsigned)z < (unsigned)GD);
                w[i] = in ? __ldg(g + (x * GD + y) * GD + z) : 1.0f;   // pad = iso+1
            }
        }

        // shared-plane (da=1) y/z edges: compute m,t once for both cells
        bool  ysm[2], zsm[2];
        float yst[2], zst[2];
        #pragma unroll
        for (int d = 0; d < 2; d++) {
            float vA = w[4 + d], vB = w[6 + d];                 // y-edge, dc=d
            ysm[d] = (vA < 0.f) != (vB < 0.f);
            yst[d] = ysm[d] ? __fdividef(vA, vA - vB) : 0.f;
        }
        #pragma unroll
        for (int d = 0; d < 2; d++) {
            float vA = w[4 + d * 2], vB = w[5 + d * 2];         // z-edge, db=d
            zsm[d] = (vA < 0.f) != (vB < 0.f);
            zst[d] = zsm[d] ? __fdividef(vA, vA - vB) : 0.f;
        }

        float vm0, vm1;
        // ---- cell0 (planes da=0,1) ----
        {
            float sx = 0.f, sy = 0.f, sz = 0.f, cnt = 0.f;
            #pragma unroll
            for (int j = 0; j < 4; j++) {                        // x-edges
                float vA = w[j], vB = w[4 + j];
                bool m = (vA < 0.f) != (vB < 0.f);
                if (m) { sx += __fdividef(vA, vA - vB); sy += (float)(j >> 1); sz += (float)(j & 1); cnt += 1.f; }
            }
            #pragma unroll
            for (int d = 0; d < 2; d++) {                        // y-edges own (da=0)
                float vA = w[d], vB = w[2 + d];
                bool m = (vA < 0.f) != (vB < 0.f);
                if (m) { sy += __fdividef(vA, vA - vB); sz += (float)d; cnt += 1.f; }
                if (ysm[d]) { sy += yst[d]; sx += 1.f; sz += (float)d; cnt += 1.f; }
            }
            #pragma unroll
            for (int d = 0; d < 2; d++) {                        // z-edges own (da=0)
                float vA = w[d * 2], vB = w[d * 2 + 1];
                bool m = (vA < 0.f) != (vB < 0.f);
                if (m) { sz += __fdividef(vA, vA - vB); sy += (float)d; cnt += 1.f; }
                if (zsm[d]) { sz += zst[d]; sx += 1.f; sy += (float)d; cnt += 1.f; }
            }
            float inv = __fdividef(1.f, fmaxf(cnt, 1.f));
            s[tid * 3 + 0] = ((float)a + sx * inv - 1.f) * nrm;
            s[tid * 3 + 1] = ((float)b + sy * inv - 1.f) * nrm;
            s[tid * 3 + 2] = ((float)c + sz * inv - 1.f) * nrm;
            vm0 = (cnt > 0.f) ? 1.f : 0.f;
        }
        // ---- cell1 (planes da=1,2) ----
        {
            float sx = 0.f, sy = 0.f, sz = 0.f, cnt = 0.f;
            #pragma unroll
            for (int j = 0; j < 4; j++) {                        // x-edges
                float vA = w[4 + j], vB = w[8 + j];
                bool m = (vA < 0.f) != (vB < 0.f);
                if (m) { sx += __fdividef(vA, vA - vB); sy += (float)(j >> 1); sz += (float)(j & 1); cnt += 1.f; }
            }
            #pragma unroll
            for (int d = 0; d < 2; d++) {                        // y: shared (da=1, dx'=0) + own (da=2, dx'=1)
                if (ysm[d]) { sy += yst[d]; sz += (float)d; cnt += 1.f; }
                float vA = w[8 + d], vB = w[10 + d];
                bool m = (vA < 0.f) != (vB < 0.f);
                if (m) { sy += __fdividef(vA, vA - vB); sx += 1.f; sz += (float)d; cnt += 1.f; }
            }
            #pragma unroll
            for (int d = 0; d < 2; d++) {                        // z: shared + own
                if (zsm[d]) { sz += zst[d]; sy += (float)d; cnt += 1.f; }
                float vA = w[8 + d * 2], vB = w[9 + d * 2];
                bool m = (vA < 0.f) != (vB < 0.f);
                if (m) { sz += __fdividef(vA, vA - vB); sx += 1.f; sy += (float)d; cnt += 1.f; }
            }
            float inv = __fdividef(1.f, fmaxf(cnt, 1.f));
            s[768 + tid * 3 + 0] = ((float)(a + 1) + sx * inv - 1.f) * nrm;
            s[768 + tid * 3 + 1] = ((float)b + sy * inv - 1.f) * nrm;
            s[768 + tid * 3 + 2] = ((float)c + sz * inv - 1.f) * nrm;
            vm1 = (cnt > 0.f) ? 1.f : 0.f;
        }

        // ---- masks + quads ----
        if (act) {
            const int cidx0 = a * C2 + rr;
            __stcs(out + VM_OFF + cidx0,      vm0);
            __stcs(out + VM_OFF + cidx0 + C2, vm1);

            const float fb0 = (float)cidx0;
            const float fb1 = fb0 + (float)C2;
            // edge-cross masks at cell min corners
            const bool s0 = w[0] < 0.f, s4 = w[4] < 0.f, s8 = w[8] < 0.f;
            const bool s2 = w[2] < 0.f, s6 = w[6] < 0.f, s10 = w[10] < 0.f;
            const bool s1 = w[1] < 0.f, s5 = w[5] < 0.f, s9 = w[9] < 0.f;

            int o0 = (a * GD + b - 1) * GD + (c - 1);        // x-quad, cell0
            int o1 = (a * C + b) * GD + (c - 1);             // y-quad, cell1 ; cell0 = -C*GD
            int o2 = (a * GD + b - 1) * C + c;               // z-quad, cell1 ; cell0 = -GD*C

            if ((b >= 1) & (c >= 1)) {
                __stcs(qb + o0,           make_float4(fb0 - 194.f, fb0 - 1.f, fb0, fb0 - 193.f));
                __stcs(qb + o0 + GD * GD, make_float4(fb1 - 194.f, fb1 - 1.f, fb1, fb1 - 193.f));
                __stcs(out + QM_OFF + o0,           (s0 != s4) ? 1.f : 0.f);
                __stcs(out + QM_OFF + o0 + GD * GD, (s4 != s8) ? 1.f : 0.f);
            }
            if (c >= 1) {
                if (a >= 1) {
                    __stcs(qb + NEX + o1 - C * GD, make_float4(fb0 - 37250.f, fb0 - 1.f, fb0, fb0 - 37249.f));
                    __stcs(out + QM_OFF + NEX + o1 - C * GD, (s0 != s2) ? 1.f : 0.f);
                }
                __stcs(qb + NEX + o1, make_float4(fb1 - 37250.f, fb1 - 1.f, fb1, fb1 - 37249.f));
                __stcs(out + QM_OFF + NEX + o1, (s4 != s6) ? 1.f : 0.f);
            }
            if (b >= 1) {
                if (a >= 1) {
                    __stcs(qb + 2 * NEX + o2 - GD * C, make_float4(fb0 - 37442.f, fb0 - 193.f, fb0, fb0 - 37249.f));
                    __stcs(out + QM_OFF + 2 * NEX + o2 - GD * C, (s0 != s1) ? 1.f : 0.f);
                }
                __stcs(qb + 2 * NEX + o2, make_float4(fb1 - 37442.f, fb1 - 193.f, fb1, fb1 - 37249.f));
                __stcs(out + QM_OFF + 2 * NEX + o2, (s4 != s5) ? 1.f : 0.f);
            }
        }

        __syncthreads();
        // verts: two contiguous regions, coalesced streaming stores
        const int F0 = 3 * (a * C2);
        #pragma unroll
        for (int i = 0; i < 3; i++) {
            int o = blockIdx.x * 768 + i * 256 + tid;
            if (o < 3 * C2) {
                __stcs(out + V_OFF + F0 + o,          s[i * 256 + tid]);
                __stcs(out + V_OFF + F0 + 3 * C2 + o, s[768 + i * 256 + tid]);
            }
        }
    } else {
        // ---------------- leftover plane: single cell a = 192 ----------------
        const int a = 192;
        const int ga = a - 1;
        float v[8];
        #pragma unroll
        for (int k = 0; k < 8; k++) {
            int x = ga + (k & 1), y = gb + ((k >> 1) & 1), z = gc + ((k >> 2) & 1);
            bool in = ((unsigned)x < (unsigned)GD) & ((unsigned)y < (unsigned)GD) & ((unsigned)z < (unsigned)GD);
            v[k] = in ? __ldg(g + (x * GD + y) * GD + z) : 1.0f;
        }
        const int EA[12] = {0,2,4,6, 0,1,4,5, 0,1,2,3};
        float sx = 0.f, sy = 0.f, sz = 0.f, cnt = 0.f;
        #pragma unroll
        for (int e = 0; e < 12; e++) {
            int axis = e >> 2;
            int A = EA[e];
            int B = A + (1 << axis);
            float vA = v[A], vB = v[B];
            bool m = (vA < 0.f) != (vB < 0.f);
            if (m) {
                float tt = __fdividef(vA, vA - vB);
                float px = (axis == 0) ? tt : (float)(A & 1);
                float py = (axis == 1) ? tt : (float)((A >> 1) & 1);
                float pz = (axis == 2) ? tt : (float)((A >> 2) & 1);
                sx += px; sy += py; sz += pz; cnt += 1.f;
            }
        }
        float inv = __fdividef(1.f, fmaxf(cnt, 1.f));
        s[tid * 3 + 0] = ((float)a + sx * inv - 1.f) * nrm;
        s[tid * 3 + 1] = ((float)b + sy * inv - 1.f) * nrm;
        s[tid * 3 + 2] = ((float)c + sz * inv - 1.f) * nrm;

        if (act) {
            const int cidx = a * C2 + rr;
            __stcs(out + VM_OFF + cidx, (cnt > 0.f) ? 1.f : 0.f);
            const float fb = (float)cidx;
            const bool s0 = v[0] < 0.f, s1 = v[1] < 0.f, s2v = v[2] < 0.f, s4v = v[4] < 0.f;
            if ((b >= 1) & (c >= 1)) {
                int o0 = (a * GD + b - 1) * GD + (c - 1);
                __stcs(qb + o0, make_float4(fb - 194.f, fb - 1.f, fb, fb - 193.f));
                __stcs(out + QM_OFF + o0, (s0 != s1) ? 1.f : 0.f);
            }
            if (c >= 1) {
                int o1 = ((a - 1) * C + b) * GD + (c - 1);
                __stcs(qb + NEX + o1, make_float4(fb - 37250.f, fb - 1.f, fb, fb - 37249.f));
                __stcs(out + QM_OFF + NEX + o1, (s0 != s2v) ? 1.f : 0.f);
            }
            if (b >= 1) {
                int o2 = ((a - 1) * GD + b - 1) * C + c;
                __stcs(qb + 2 * NEX + o2, make_float4(fb - 37442.f, fb - 193.f, fb, fb - 37249.f));
                __stcs(out + QM_OFF + 2 * NEX + o2, (s0 != s4v) ? 1.f : 0.f);
            }
        }

        __syncthreads();
        const int F0 = 3 * (a * C2);
        #pragma unroll
        for (int i = 0; i < 3; i++) {
            int o = blockIdx.x * 768 + i * 256 + tid;
            if (o < 3 * C2) __stcs(out + V_OFF + F0 + o, s[i * 256 + tid]);
        }
    }
}

extern "C" void kernel_launch(void* const* d_in, const int* in_sizes, int n_in,
                              void* d_out, int out_size)
{
    const float* g = (const float*)d_in[0];
    float* out = (float*)d_out;
    dim3 grid(BX, 97, 1);
    dmc_pair<<<grid, 256>>>(g, out);
}

// round 6
// speedup vs baseline: 1.0165x; 1.0165x over previous
#include <cuda_runtime.h>
#include <cuda_bf16.h>

// Dual marching cubes, GRID=192, ISO=0.
// R6: R4 structure (1 cell/thread, occ ~96%) + 2D grid (a = blockIdx.y),
// rr-based quad offsets, quad stores issued before grid loads.
// Output (float32, concatenated, reference order):
//   verts  [193^3 * 3]       at V_OFF  = 0
//   vmask  [193^3]           at VM_OFF = 21,567,171
//   quads  [3*193*192*192*4] at Q_OFF  = 28,756,228   (16B-aligned)
//   qmask  [3*193*192*192]   at QM_OFF = 114,133,252  (16B-aligned)

#define GD   192
#define C    193
#define C2   (C*C)          // 37249
#define NC   (C*C*C)        // 7,189,057
#define NEX  (C*GD*GD)      // 7,114,752
#define NQ   (3*NEX)
#define V_OFF  0
#define VM_OFF (3*NC)
#define Q_OFF  (VM_OFF + NC)
#define QM_OFF (Q_OFF + 4*NQ)

#define BX 146              // 146*256 = 37376 >= C2

__global__ void __launch_bounds__(256)
dmc6(const float* __restrict__ g, float* __restrict__ out)
{
    __shared__ float s[768];
    const int tid = threadIdx.x;
    const int a   = blockIdx.y;                 // slab (uniform per block)
    const int rr0 = blockIdx.x * 256;
    const int r   = rr0 + tid;
    const bool act = r < C2;
    const int rr  = act ? r : C2 - 1;
    const int b   = rr / C;
    const int c   = rr - b * C;
    const int cidx = a * C2 + rr;

    float4* qb = (float4*)(out + Q_OFF);

    // ---------------- quads first: pure function of index, store early ----------------
    if (act) {
        const float fb = (float)cidx;
        // o0 = (a*192 + b-1)*192 + (c-1) = 36864*a + rr - b - 193
        // o1 = ((a-1)*193 + b)*192 + (c-1) = 37056*a - 37056 + rr - b - 1
        // o2 = ((a-1)*192 + b-1)*193 + c  = 37056*a - 37056 + rr - 193
        const int t1 = 37056 * a - 37056 + rr;
        if ((b >= 1) & (c >= 1)) {
            int o0 = 36864 * a + rr - b - 193;
            __stcs(qb + o0, make_float4(fb - 194.f, fb - 1.f, fb, fb - 193.f));
        }
        if ((a >= 1) & (c >= 1)) {
            int o1 = t1 - b - 1;
            __stcs(qb + NEX + o1, make_float4(fb - 37250.f, fb - 1.f, fb, fb - 37249.f));
        }
        if ((a >= 1) & (b >= 1)) {
            int o2 = t1 - 193;
            __stcs(qb + 2 * NEX + o2, make_float4(fb - 37442.f, fb - 193.f, fb, fb - 37249.f));
        }
    }

    // ---------------- corner loads ----------------
    // corner k: dx=k&1 (a), dy=(k>>1)&1 (b), dz=(k>>2)&1 (c); P[a+dx, b+dy, c+dz]
    float v[8];
    const int ga = a - 1, gb = b - 1, gc = c - 1;
    const bool interior = (a >= 1) & (a <= GD - 1) & (b >= 1) & (b <= GD - 1) & (c >= 1) & (c <= GD - 1);
    if (interior) {
        const float* p = g + ((ga * GD + gb) * GD + gc);
        #pragma unroll
        for (int k = 0; k < 8; k++) {
            int dx = k & 1, dy = (k >> 1) & 1, dz = (k >> 2) & 1;
            v[k] = __ldg(p + (dx * GD + dy) * GD + dz);
        }
    } else {
        #pragma unroll
        for (int k = 0; k < 8; k++) {
            int x = ga + (k & 1), y = gb + ((k >> 1) & 1), z = gc + ((k >> 2) & 1);
            bool in = ((unsigned)x < (unsigned)GD) & ((unsigned)y < (unsigned)GD) & ((unsigned)z < (unsigned)GD);
            v[k] = in ? __ldg(g + (x * GD + y) * GD + z) : 1.0f;   // pad = iso+1
        }
    }

    // ---------------- qmask (needs only 4 corner signs) ----------------
    if (act) {
        const bool s0 = v[0] < 0.f, s1 = v[1] < 0.f, s2v = v[2] < 0.f, s4v = v[4] < 0.f;
        const int t1 = 37056 * a - 37056 + rr;
        if ((b >= 1) & (c >= 1))
            __stcs(out + QM_OFF + (36864 * a + rr - b - 193), (s0 != s1) ? 1.f : 0.f);
        if ((a >= 1) & (c >= 1))
            __stcs(out + QM_OFF + NEX + (t1 - b - 1), (s0 != s2v) ? 1.f : 0.f);
        if ((a >= 1) & (b >= 1))
            __stcs(out + QM_OFF + 2 * NEX + (t1 - 193), (s0 != s4v) ? 1.f : 0.f);
    }

    // ---------------- vertex: 12-edge crossing mean ----------------
    const int EA[12] = {0,2,4,6, 0,1,4,5, 0,1,2,3};
    float sx = 0.f, sy = 0.f, sz = 0.f, cnt = 0.f;
    #pragma unroll
    for (int e = 0; e < 12; e++) {
        int axis = e >> 2;
        int A = EA[e];
        int B = A + (1 << axis);
        float vA = v[A], vB = v[B];
        bool m = (vA < 0.f) != (vB < 0.f);
        if (m) {
            float tt = __fdividef(vA, vA - vB);   // == (0 - vA)/(vB - vA)
            float px = (axis == 0) ? tt : (float)(A & 1);
            float py = (axis == 1) ? tt : (float)((A >> 1) & 1);
            float pz = (axis == 2) ? tt : (float)((A >> 2) & 1);
            sx += px; sy += py; sz += pz; cnt += 1.f;
        }
    }

    const float inv = __fdividef(1.f, fmaxf(cnt, 1.f));
    const float nrm = 1.0f / (float)(GD - 1);
    float fx = ((float)a + sx * inv - 1.f) * nrm;
    float fy = ((float)b + sy * inv - 1.f) * nrm;
    float fz = ((float)c + sz * inv - 1.f) * nrm;

    if (act) __stcs(out + VM_OFF + cidx, (cnt > 0.f) ? 1.f : 0.f);

    // ---------------- vert stores: stage stride-3 via smem -> coalesced ----------------
    s[tid * 3 + 0] = fx;
    s[tid * 3 + 1] = fy;
    s[tid * 3 + 2] = fz;
    __syncthreads();
    const int vbase = 3 * (a * C2 + rr0);
    const int lim   = 3 * (C2 - rr0);        // elements valid in this block's region
    #pragma unroll
    for (int i = 0; i < 3; i++) {
        int o = i * 256 + tid;
        if (o < lim) __stcs(out + V_OFF + vbase + o, s[o]);
    }
}

extern "C" void kernel_launch(void* const* d_in, const int* in_sizes, int n_in,
                              void* d_out, int out_size)
{
    const float* g = (const float*)d_in[0];
    float* out = (float*)d_out;
    dim3 grid(BX, C, 1);
    dmc6<<<grid, 256>>>(g, out);
}